// round 1
// baseline (speedup 1.0000x reference)
#include <cuda_runtime.h>
#include <cuda_bf16.h>
#include <mma.h>

using namespace nvcuda;

// Problem constants
#define Bn 4
#define Tn 4096
#define Dn 1024
#define Hn 16
#define HDn 64
#define Mrows (Bn * Tn)          // 16384
#define QKV_N (3 * Dn)           // 3072

// Scratch (device globals: allocation-free)
__device__ float g_qkv[(size_t)Mrows * QKV_N];    // 192 MB
__device__ float g_attn[(size_t)Mrows * Dn];      // 64 MB

// ---------------------------------------------------------------------------
// TF32 WMMA GEMM: C[M,N] = A[M,K] @ B[K,N], all row-major fp32.
// Block tile 128x128, K-tile 32, 8 warps (2x4), warp tile 64x32 (4x2 wmma).
// ---------------------------------------------------------------------------
#define BM 128
#define BN 128
#define BK 32
#define PAD_A 4
#define PAD_B 4

__global__ __launch_bounds__(256, 1)
void gemm_tf32_kernel(const float* __restrict__ A,
                      const float* __restrict__ B,
                      float* __restrict__ C,
                      int M, int N, int K)
{
    __shared__ __align__(16) float As[BM][BK + PAD_A];   // 128 x 36
    __shared__ __align__(16) float Bs[BK][BN + PAD_B];   // 32 x 132

    const int tid = threadIdx.x;
    const int warpId = tid >> 5;
    const int warpRow = warpId >> 2;      // 0..1  (64 rows each)
    const int warpCol = warpId & 3;       // 0..3  (32 cols each)

    const int rowBase = blockIdx.y * BM;
    const int colBase = blockIdx.x * BN;

    wmma::fragment<wmma::accumulator, 16, 16, 8, float> acc[4][2];
    #pragma unroll
    for (int m = 0; m < 4; m++)
        #pragma unroll
        for (int n = 0; n < 2; n++)
            wmma::fill_fragment(acc[m][n], 0.0f);

    for (int k0 = 0; k0 < K; k0 += BK) {
        // Load A tile: 128 x 32 = 1024 float4, 4 per thread
        #pragma unroll
        for (int l = tid; l < BM * (BK / 4); l += 256) {
            int r = l >> 3;
            int c = (l & 7) << 2;
            float4 v = *reinterpret_cast<const float4*>(
                A + (size_t)(rowBase + r) * K + k0 + c);
            *reinterpret_cast<float4*>(&As[r][c]) = v;
        }
        // Load B tile: 32 x 128 = 1024 float4, 4 per thread
        #pragma unroll
        for (int l = tid; l < BK * (BN / 4); l += 256) {
            int r = l >> 5;
            int c = (l & 31) << 2;
            float4 v = *reinterpret_cast<const float4*>(
                B + (size_t)(k0 + r) * N + colBase + c);
            *reinterpret_cast<float4*>(&Bs[r][c]) = v;
        }
        __syncthreads();

        #pragma unroll
        for (int kk = 0; kk < BK / 8; kk++) {
            wmma::fragment<wmma::matrix_a, 16, 16, 8, wmma::precision::tf32, wmma::row_major> af[4];
            wmma::fragment<wmma::matrix_b, 16, 16, 8, wmma::precision::tf32, wmma::row_major> bf[2];
            #pragma unroll
            for (int m = 0; m < 4; m++) {
                wmma::load_matrix_sync(af[m], &As[warpRow * 64 + m * 16][kk * 8], BK + PAD_A);
                #pragma unroll
                for (int t = 0; t < af[m].num_elements; t++)
                    af[m].x[t] = wmma::__float_to_tf32(af[m].x[t]);
            }
            #pragma unroll
            for (int n = 0; n < 2; n++) {
                wmma::load_matrix_sync(bf[n], &Bs[kk * 8][warpCol * 32 + n * 16], BN + PAD_B);
                #pragma unroll
                for (int t = 0; t < bf[n].num_elements; t++)
                    bf[n].x[t] = wmma::__float_to_tf32(bf[n].x[t]);
            }
            #pragma unroll
            for (int m = 0; m < 4; m++)
                #pragma unroll
                for (int n = 0; n < 2; n++)
                    wmma::mma_sync(acc[m][n], af[m], bf[n], acc[m][n]);
        }
        __syncthreads();
    }

    // Epilogue: direct global store
    #pragma unroll
    for (int m = 0; m < 4; m++) {
        #pragma unroll
        for (int n = 0; n < 2; n++) {
            int r = rowBase + warpRow * 64 + m * 16;
            int c = colBase + warpCol * 32 + n * 16;
            wmma::store_matrix_sync(C + (size_t)r * N + c, acc[m][n], N, wmma::mem_row_major);
        }
    }
}

// ---------------------------------------------------------------------------
// Per-token head-attention: one block per token (16384 blocks, 256 threads).
// q,k,v are 16x64 tiles at qkv[t*3072 + {0,1024,2048}].
// scores = q k^T / 8 (16x16), softmax over j, out = attn @ v (16x64).
// ---------------------------------------------------------------------------
__global__ __launch_bounds__(256, 8)
void attn_kernel(const float* __restrict__ qkv, float* __restrict__ out)
{
    __shared__ float sq[16 * 64];
    __shared__ float sk[16 * 65];   // padded rows: conflict-free strided reads
    __shared__ float sv[16 * 64];
    __shared__ float sattn[16 * 16];

    const int t = blockIdx.x;
    const float* base = qkv + (size_t)t * QKV_N;
    const int tid = threadIdx.x;

    #pragma unroll
    for (int idx = tid; idx < 1024; idx += 256) {
        int r = idx >> 6, d = idx & 63;
        sq[idx]          = base[idx];
        sk[r * 65 + d]   = base[1024 + idx];
        sv[idx]          = base[2048 + idx];
    }
    __syncthreads();

    // scores: tid -> (i = tid/16, j = tid%16)
    const int i = tid >> 4, j = tid & 15;
    float s = 0.0f;
    #pragma unroll
    for (int d = 0; d < 64; d++)
        s += sq[i * 64 + d] * sk[j * 65 + d];
    s *= 0.125f;   // 1/sqrt(64)

    // softmax over j — 16-lane groups are warp-aligned
    float mx = s;
    #pragma unroll
    for (int off = 8; off; off >>= 1)
        mx = fmaxf(mx, __shfl_xor_sync(0xffffffffu, mx, off));
    float e = __expf(s - mx);
    float sum = e;
    #pragma unroll
    for (int off = 8; off; off >>= 1)
        sum += __shfl_xor_sync(0xffffffffu, sum, off);
    sattn[i * 16 + j] = e / sum;
    __syncthreads();

    // out = attn @ v : 1024 outputs, 4 per thread
    #pragma unroll
    for (int idx = tid; idx < 1024; idx += 256) {
        int oi = idx >> 6, od = idx & 63;
        float acc = 0.0f;
        #pragma unroll
        for (int jj = 0; jj < 16; jj++)
            acc += sattn[oi * 16 + jj] * sv[jj * 64 + od];
        out[(size_t)t * Dn + idx] = acc;
    }
}

// ---------------------------------------------------------------------------
extern "C" void kernel_launch(void* const* d_in, const int* in_sizes, int n_in,
                              void* d_out, int out_size)
{
    const float* x    = (const float*)d_in[0];   // (4,4096,1024)
    const float* Wqkv = (const float*)d_in[1];   // (1024,3072)
    const float* Wout = (const float*)d_in[2];   // (1024,1024)
    float* out = (float*)d_out;

    float* qkv_ptr = nullptr;
    float* attn_ptr = nullptr;
    cudaGetSymbolAddress((void**)&qkv_ptr, g_qkv);
    cudaGetSymbolAddress((void**)&attn_ptr, g_attn);

    // GEMM1: qkv = x @ Wqkv   (16384 x 3072, K=1024)
    {
        dim3 grid(QKV_N / BN, Mrows / BM);
        gemm_tf32_kernel<<<grid, 256>>>(x, Wqkv, qkv_ptr, Mrows, QKV_N, Dn);
    }

    // Attention per token
    attn_kernel<<<Mrows, 256>>>(qkv_ptr, attn_ptr);

    // GEMM2: out = attn @ Wout  (16384 x 1024, K=1024)
    {
        dim3 grid(Dn / BN, Mrows / BM);
        gemm_tf32_kernel<<<grid, 256>>>(attn_ptr, Wout, out, Mrows, Dn, Dn);
    }
}

// round 3
// speedup vs baseline: 1.0556x; 1.0556x over previous
#include <cstdint>
#include <cuda_runtime.h>
#include <cuda_bf16.h>
#include <mma.h>

using namespace nvcuda;

// Problem constants
#define Bn 4
#define Tn 4096
#define Dn 1024
#define Hn 16
#define HDn 64
#define Mrows (Bn * Tn)          // 16384
#define QKV_N (3 * Dn)           // 3072

// Scratch (device globals: allocation-free)
__device__ float g_qkv[(size_t)Mrows * QKV_N];    // 192 MB
__device__ float g_attn[(size_t)Mrows * Dn];      // 64 MB

// ---------------------------------------------------------------------------
// TF32 WMMA GEMM with 3-stage cp.async pipeline.
// C[M,N] = A[M,K] @ B[K,N], all row-major fp32.
// Block tile 128x128, K-tile 32, 8 warps (2x4), warp tile 64x32 (4x2 wmma).
// ---------------------------------------------------------------------------
#define BM 128
#define BN 128
#define BK 32
#define STAGES 3
#define A_LD (BK + 4)            // 36 floats (144B, multiple of 16B)
#define B_LD (BN + 4)            // 132 floats (528B, multiple of 16B)
#define A_STAGE (BM * A_LD)      // 4608 floats
#define B_STAGE (BK * B_LD)      // 4224 floats
#define SMEM_FLOATS (STAGES * (A_STAGE + B_STAGE))
#define SMEM_BYTES (SMEM_FLOATS * 4)   // 105984 bytes

__device__ __forceinline__ void cp_async16(float* smem_dst, const float* gmem_src) {
    unsigned int s = (unsigned int)__cvta_generic_to_shared(smem_dst);
    asm volatile("cp.async.cg.shared.global [%0], [%1], 16;\n" :: "r"(s), "l"(gmem_src));
}
__device__ __forceinline__ void cp_commit() {
    asm volatile("cp.async.commit_group;\n" ::);
}
template<int N>
__device__ __forceinline__ void cp_wait() {
    asm volatile("cp.async.wait_group %0;\n" :: "n"(N));
}

__global__ __launch_bounds__(256)
void gemm_tf32_pipe_kernel(const float* __restrict__ A,
                           const float* __restrict__ B,
                           float* __restrict__ C,
                           int M, int N, int K)
{
    extern __shared__ float smem[];
    float* As = smem;                         // [STAGES][BM][A_LD]
    float* Bs = smem + STAGES * A_STAGE;      // [STAGES][BK][B_LD]

    const int tid = threadIdx.x;
    const int warpId = tid >> 5;
    const int warpRow = warpId >> 2;      // 0..1  (64 rows each)
    const int warpCol = warpId & 3;       // 0..3  (32 cols each)

    const int rowBase = blockIdx.y * BM;
    const int colBase = blockIdx.x * BN;

    const int KT = K / BK;

    auto load_stage = [&](int kt, int stage) {
        const float* Ag = A + (size_t)rowBase * K + kt * BK;
        const float* Bg = B + (size_t)(kt * BK) * N + colBase;
        float* Asm = As + stage * A_STAGE;
        float* Bsm = Bs + stage * B_STAGE;
        #pragma unroll
        for (int i = 0; i < 4; i++) {
            int l = tid + i * 256;
            int ar = l >> 3, ac = (l & 7) << 2;
            cp_async16(Asm + ar * A_LD + ac, Ag + (size_t)ar * K + ac);
            int br = l >> 5, bc = (l & 31) << 2;
            cp_async16(Bsm + br * B_LD + bc, Bg + (size_t)br * N + bc);
        }
        cp_commit();
    };

    // Prefetch first STAGES-1 stages
    #pragma unroll
    for (int s = 0; s < STAGES - 1; s++)
        load_stage(s, s);

    wmma::fragment<wmma::accumulator, 16, 16, 8, float> acc[4][2];
    #pragma unroll
    for (int m = 0; m < 4; m++)
        #pragma unroll
        for (int n = 0; n < 2; n++)
            wmma::fill_fragment(acc[m][n], 0.0f);

    for (int kt = 0; kt < KT; kt++) {
        cp_wait<STAGES - 2>();
        __syncthreads();

        // Issue loads for the stage STAGES-1 ahead (overlaps with compute below)
        if (kt + STAGES - 1 < KT)
            load_stage(kt + STAGES - 1, (kt + STAGES - 1) % STAGES);

        const float* Asm = As + (kt % STAGES) * A_STAGE;
        const float* Bsm = Bs + (kt % STAGES) * B_STAGE;

        #pragma unroll
        for (int kk = 0; kk < BK / 8; kk++) {
            wmma::fragment<wmma::matrix_a, 16, 16, 8, wmma::precision::tf32, wmma::row_major> af[4];
            wmma::fragment<wmma::matrix_b, 16, 16, 8, wmma::precision::tf32, wmma::row_major> bf[2];
            #pragma unroll
            for (int m = 0; m < 4; m++) {
                wmma::load_matrix_sync(af[m], Asm + (warpRow * 64 + m * 16) * A_LD + kk * 8, A_LD);
                #pragma unroll
                for (int t = 0; t < af[m].num_elements; t++)
                    af[m].x[t] = wmma::__float_to_tf32(af[m].x[t]);
            }
            #pragma unroll
            for (int n = 0; n < 2; n++) {
                wmma::load_matrix_sync(bf[n], Bsm + (kk * 8) * B_LD + warpCol * 32 + n * 16, B_LD);
                #pragma unroll
                for (int t = 0; t < bf[n].num_elements; t++)
                    bf[n].x[t] = wmma::__float_to_tf32(bf[n].x[t]);
            }
            #pragma unroll
            for (int m = 0; m < 4; m++)
                #pragma unroll
                for (int n = 0; n < 2; n++)
                    wmma::mma_sync(acc[m][n], af[m], bf[n], acc[m][n]);
        }
        __syncthreads();
    }

    // Epilogue: direct global store
    #pragma unroll
    for (int m = 0; m < 4; m++) {
        #pragma unroll
        for (int n = 0; n < 2; n++) {
            int r = rowBase + warpRow * 64 + m * 16;
            int c = colBase + warpCol * 32 + n * 16;
            wmma::store_matrix_sync(C + (size_t)r * N + c, acc[m][n], N, wmma::mem_row_major);
        }
    }
}

// ---------------------------------------------------------------------------
// Per-token head-attention: one block per token (16384 blocks, 256 threads).
// ---------------------------------------------------------------------------
__global__ __launch_bounds__(256, 8)
void attn_kernel(const float* __restrict__ qkv, float* __restrict__ out)
{
    __shared__ float sq[16 * 64];
    __shared__ float sk[16 * 65];   // padded rows: conflict-free strided reads
    __shared__ float sv[16 * 64];
    __shared__ float sattn[16 * 16];

    const int t = blockIdx.x;
    const float* base = qkv + (size_t)t * QKV_N;
    const int tid = threadIdx.x;

    #pragma unroll
    for (int idx = tid; idx < 1024; idx += 256) {
        int r = idx >> 6, d = idx & 63;
        sq[idx]          = base[idx];
        sk[r * 65 + d]   = base[1024 + idx];
        sv[idx]          = base[2048 + idx];
    }
    __syncthreads();

    const int i = tid >> 4, j = tid & 15;
    float s = 0.0f;
    #pragma unroll
    for (int d = 0; d < 64; d++)
        s += sq[i * 64 + d] * sk[j * 65 + d];
    s *= 0.125f;   // 1/sqrt(64)

    float mx = s;
    #pragma unroll
    for (int off = 8; off; off >>= 1)
        mx = fmaxf(mx, __shfl_xor_sync(0xffffffffu, mx, off));
    float e = __expf(s - mx);
    float sum = e;
    #pragma unroll
    for (int off = 8; off; off >>= 1)
        sum += __shfl_xor_sync(0xffffffffu, sum, off);
    sattn[i * 16 + j] = e / sum;
    __syncthreads();

    #pragma unroll
    for (int idx = tid; idx < 1024; idx += 256) {
        int oi = idx >> 6, od = idx & 63;
        float acc = 0.0f;
        #pragma unroll
        for (int jj = 0; jj < 16; jj++)
            acc += sattn[oi * 16 + jj] * sv[jj * 64 + od];
        out[(size_t)t * Dn + idx] = acc;
    }
}

// ---------------------------------------------------------------------------
extern "C" void kernel_launch(void* const* d_in, const int* in_sizes, int n_in,
                              void* d_out, int out_size)
{
    const float* x    = (const float*)d_in[0];   // (4,4096,1024)
    const float* Wqkv = (const float*)d_in[1];   // (1024,3072)
    const float* Wout = (const float*)d_in[2];   // (1024,1024)
    float* out = (float*)d_out;

    float* qkv_ptr = nullptr;
    float* attn_ptr = nullptr;
    cudaGetSymbolAddress((void**)&qkv_ptr, g_qkv);
    cudaGetSymbolAddress((void**)&attn_ptr, g_attn);

    static bool attr_set = false;
    if (!attr_set) {
        cudaFuncSetAttribute(gemm_tf32_pipe_kernel,
                             cudaFuncAttributeMaxDynamicSharedMemorySize, SMEM_BYTES);
        attr_set = true;
    }

    // GEMM1: qkv = x @ Wqkv   (16384 x 3072, K=1024)
    {
        dim3 grid(QKV_N / BN, Mrows / BM);
        gemm_tf32_pipe_kernel<<<grid, 256, SMEM_BYTES>>>(x, Wqkv, qkv_ptr, Mrows, QKV_N, Dn);
    }

    // Attention per token
    attn_kernel<<<Mrows, 256>>>(qkv_ptr, attn_ptr);

    // GEMM2: out = attn @ Wout  (16384 x 1024, K=1024)
    {
        dim3 grid(Dn / BN, Mrows / BM);
        gemm_tf32_pipe_kernel<<<grid, 256, SMEM_BYTES>>>(attn_ptr, Wout, out, Mrows, Dn, Dn);
    }
}

// round 5
// speedup vs baseline: 1.2056x; 1.1421x over previous
#include <cstdint>
#include <cuda_runtime.h>
#include <cuda_bf16.h>
#include <mma.h>

using namespace nvcuda;

// Problem constants
#define Mrows 16384
#define QKV_N 3072
#define Dn 1024

// Scratch (device globals: allocation-free)
__device__ float g_qkv[(size_t)Mrows * QKV_N];    // 192 MB
__device__ float g_attn[(size_t)Mrows * Dn];      // 64 MB
__device__ float g_xr[(size_t)Mrows * Dn];        // 64 MB  (tf32-rounded x)
__device__ float g_wqkvr[(size_t)Dn * QKV_N];     // 12 MB  (tf32-rounded Wqkv)
__device__ float g_woutr[(size_t)Dn * Dn];        // 4 MB   (tf32-rounded Wout)

__device__ __forceinline__ float round_tf32(float x) {
    unsigned u;
    asm("cvt.rn.tf32.f32 %0, %1;" : "=r"(u) : "f"(x));
    return __uint_as_float(u);
}

__device__ __forceinline__ void cp_async16(float* smem_dst, const float* gmem_src) {
    unsigned s = (unsigned)__cvta_generic_to_shared(smem_dst);
    asm volatile("cp.async.cg.shared.global [%0], [%1], 16;\n" :: "r"(s), "l"(gmem_src));
}
__device__ __forceinline__ void cp_commit() {
    asm volatile("cp.async.commit_group;\n" ::);
}
template<int N>
__device__ __forceinline__ void cp_wait() {
    asm volatile("cp.async.wait_group %0;\n" :: "n"(N));
}

// ---------------------------------------------------------------------------
// TF32 WMMA GEMM, 3-stage cp.async pipeline, 256x128 block tile, 64x64 warp
// tile (8 warps, 4x2). Inputs MUST be pre-rounded to tf32 (no in-loop cvt).
// ---------------------------------------------------------------------------
#define BM 256
#define BN 128
#define BK 32
#define STAGES 3
#define A_LD (BK + 4)            // 36 floats
#define B_LD (BN + 4)            // 132 floats
#define A_STAGE (BM * A_LD)      // 9216 floats
#define B_STAGE (BK * B_LD)      // 4224 floats
#define SMEM_FLOATS (STAGES * (A_STAGE + B_STAGE))
#define SMEM_BYTES (SMEM_FLOATS * 4)   // 161280 bytes

__global__ __launch_bounds__(256)
void gemm_tf32_pipe_kernel(const float* __restrict__ A,
                           const float* __restrict__ B,
                           float* __restrict__ C,
                           int M, int N, int K)
{
    extern __shared__ float smem[];
    float* As = smem;                         // [STAGES][BM][A_LD]
    float* Bs = smem + STAGES * A_STAGE;      // [STAGES][BK][B_LD]

    const int tid = threadIdx.x;
    const int warpId = tid >> 5;
    const int warpRow = warpId >> 1;      // 0..3  (64 rows each)
    const int warpCol = warpId & 1;       // 0..1  (64 cols each)

    const int rowBase = blockIdx.y * BM;
    const int colBase = blockIdx.x * BN;

    const int KT = K / BK;

    auto load_stage = [&](int kt, int stage) {
        const float* Ag = A + (size_t)rowBase * K + kt * BK;
        const float* Bg = B + (size_t)(kt * BK) * N + colBase;
        float* Asm = As + stage * A_STAGE;
        float* Bsm = Bs + stage * B_STAGE;
        // A tile: 256x32 floats = 2048 float4, 8 per thread
        #pragma unroll
        for (int i = 0; i < 8; i++) {
            int l = tid + i * 256;
            int ar = l >> 3, ac = (l & 7) << 2;
            cp_async16(Asm + ar * A_LD + ac, Ag + (size_t)ar * K + ac);
        }
        // B tile: 32x128 floats = 1024 float4, 4 per thread
        #pragma unroll
        for (int i = 0; i < 4; i++) {
            int l = tid + i * 256;
            int br = l >> 5, bc = (l & 31) << 2;
            cp_async16(Bsm + br * B_LD + bc, Bg + (size_t)br * N + bc);
        }
        cp_commit();
    };

    // Prefetch first STAGES-1 stages
    #pragma unroll
    for (int s = 0; s < STAGES - 1; s++)
        load_stage(s, s);

    wmma::fragment<wmma::accumulator, 16, 16, 8, float> acc[4][4];
    #pragma unroll
    for (int m = 0; m < 4; m++)
        #pragma unroll
        for (int n = 0; n < 4; n++)
            wmma::fill_fragment(acc[m][n], 0.0f);

    for (int kt = 0; kt < KT; kt++) {
        cp_wait<STAGES - 2>();
        __syncthreads();

        // Issue loads for the stage STAGES-1 ahead (overlaps with compute)
        if (kt + STAGES - 1 < KT)
            load_stage(kt + STAGES - 1, (kt + STAGES - 1) % STAGES);

        const float* Asm = As + (kt % STAGES) * A_STAGE;
        const float* Bsm = Bs + (kt % STAGES) * B_STAGE;

        #pragma unroll
        for (int kk = 0; kk < BK / 8; kk++) {
            wmma::fragment<wmma::matrix_a, 16, 16, 8, wmma::precision::tf32, wmma::row_major> af[4];
            wmma::fragment<wmma::matrix_b, 16, 16, 8, wmma::precision::tf32, wmma::row_major> bf[4];
            #pragma unroll
            for (int m = 0; m < 4; m++)
                wmma::load_matrix_sync(af[m], Asm + (warpRow * 64 + m * 16) * A_LD + kk * 8, A_LD);
            #pragma unroll
            for (int n = 0; n < 4; n++)
                wmma::load_matrix_sync(bf[n], Bsm + (kk * 8) * B_LD + warpCol * 64 + n * 16, B_LD);
            // NOTE: no per-element tf32 cvt — inputs are pre-rounded, HW
            // truncation of already-rounded values is exact.
            #pragma unroll
            for (int m = 0; m < 4; m++)
                #pragma unroll
                for (int n = 0; n < 4; n++)
                    wmma::mma_sync(acc[m][n], af[m], bf[n], acc[m][n]);
        }
        __syncthreads();
    }

    // Epilogue: direct global store
    #pragma unroll
    for (int m = 0; m < 4; m++) {
        #pragma unroll
        for (int n = 0; n < 4; n++) {
            int r = rowBase + warpRow * 64 + m * 16;
            int c = colBase + warpCol * 64 + n * 16;
            wmma::store_matrix_sync(C + (size_t)r * N + c, acc[m][n], N, wmma::mem_row_major);
        }
    }
}

// ---------------------------------------------------------------------------
// Elementwise tf32 RN rounding (pre-round GEMM operands)
// ---------------------------------------------------------------------------
__global__ void round_tf32_kernel(const float4* __restrict__ in,
                                  float4* __restrict__ out, int n4)
{
    int i = blockIdx.x * blockDim.x + threadIdx.x;
    if (i < n4) {
        float4 v = in[i];
        v.x = round_tf32(v.x); v.y = round_tf32(v.y);
        v.z = round_tf32(v.z); v.w = round_tf32(v.w);
        out[i] = v;
    }
}

// ---------------------------------------------------------------------------
// Per-token head-attention: one block per token. Output tf32-rounded
// (feeds GEMM2 without in-loop conversion).
// ---------------------------------------------------------------------------
__global__ __launch_bounds__(256, 8)
void attn_kernel(const float* __restrict__ qkv, float* __restrict__ out)
{
    __shared__ float sq[16 * 64];
    __shared__ float sk[16 * 65];
    __shared__ float sv[16 * 64];
    __shared__ float sattn[16 * 16];

    const int t = blockIdx.x;
    const float* base = qkv + (size_t)t * QKV_N;
    const int tid = threadIdx.x;

    #pragma unroll
    for (int idx = tid; idx < 1024; idx += 256) {
        int r = idx >> 6, d = idx & 63;
        sq[idx]        = base[idx];
        sk[r * 65 + d] = base[1024 + idx];
        sv[idx]        = base[2048 + idx];
    }
    __syncthreads();

    const int i = tid >> 4, j = tid & 15;
    float s = 0.0f;
    #pragma unroll
    for (int d = 0; d < 64; d++)
        s += sq[i * 64 + d] * sk[j * 65 + d];
    s *= 0.125f;

    float mx = s;
    #pragma unroll
    for (int off = 8; off; off >>= 1)
        mx = fmaxf(mx, __shfl_xor_sync(0xffffffffu, mx, off));
    float e = __expf(s - mx);
    float sum = e;
    #pragma unroll
    for (int off = 8; off; off >>= 1)
        sum += __shfl_xor_sync(0xffffffffu, sum, off);
    sattn[i * 16 + j] = e / sum;
    __syncthreads();

    #pragma unroll
    for (int idx = tid; idx < 1024; idx += 256) {
        int oi = idx >> 6, od = idx & 63;
        float acc = 0.0f;
        #pragma unroll
        for (int jj = 0; jj < 16; jj++)
            acc += sattn[oi * 16 + jj] * sv[jj * 64 + od];
        out[(size_t)t * Dn + idx] = round_tf32(acc);
    }
}

// ---------------------------------------------------------------------------
extern "C" void kernel_launch(void* const* d_in, const int* in_sizes, int n_in,
                              void* d_out, int out_size)
{
    const float* x    = (const float*)d_in[0];
    const float* Wqkv = (const float*)d_in[1];
    const float* Wout = (const float*)d_in[2];
    float* out = (float*)d_out;

    float *qkv_p, *attn_p, *xr_p, *wqkvr_p, *woutr_p;
    cudaGetSymbolAddress((void**)&qkv_p, g_qkv);
    cudaGetSymbolAddress((void**)&attn_p, g_attn);
    cudaGetSymbolAddress((void**)&xr_p, g_xr);
    cudaGetSymbolAddress((void**)&wqkvr_p, g_wqkvr);
    cudaGetSymbolAddress((void**)&woutr_p, g_woutr);

    static bool attr_set = false;
    if (!attr_set) {
        cudaFuncSetAttribute(gemm_tf32_pipe_kernel,
                             cudaFuncAttributeMaxDynamicSharedMemorySize, SMEM_BYTES);
        attr_set = true;
    }

    // Pre-round operands to tf32 (RN) once.
    {
        int n4x = (Mrows * Dn) / 4;
        round_tf32_kernel<<<(n4x + 255) / 256, 256>>>((const float4*)x, (float4*)xr_p, n4x);
        int n4q = (Dn * QKV_N) / 4;
        round_tf32_kernel<<<(n4q + 255) / 256, 256>>>((const float4*)Wqkv, (float4*)wqkvr_p, n4q);
        int n4o = (Dn * Dn) / 4;
        round_tf32_kernel<<<(n4o + 255) / 256, 256>>>((const float4*)Wout, (float4*)woutr_p, n4o);
    }

    // GEMM1: qkv = x @ Wqkv   (16384 x 3072, K=1024)
    {
        dim3 grid(QKV_N / BN, Mrows / BM);
        gemm_tf32_pipe_kernel<<<grid, 256, SMEM_BYTES>>>(xr_p, wqkvr_p, qkv_p,
                                                         Mrows, QKV_N, Dn);
    }

    // Attention per token
    attn_kernel<<<Mrows, 256>>>(qkv_p, attn_p);

    // GEMM2: out = attn @ Wout  (16384 x 1024, K=1024)
    {
        dim3 grid(Dn / BN, Mrows / BM);
        gemm_tf32_pipe_kernel<<<grid, 256, SMEM_BYTES>>>(attn_p, woutr_p, out,
                                                         Mrows, Dn, Dn);
    }
}

// round 6
// speedup vs baseline: 1.3007x; 1.0789x over previous
#include <cstdint>
#include <cuda_runtime.h>
#include <cuda_bf16.h>
#include <mma.h>

using namespace nvcuda;

// Problem constants
#define Mrows 16384
#define QKV_N 3072
#define Dn 1024

// Scratch (device globals: allocation-free)
__device__ float g_qkv[(size_t)Mrows * QKV_N];    // 192 MB
__device__ float g_attn[(size_t)Mrows * Dn];      // 64 MB
__device__ float g_xr[(size_t)Mrows * Dn];        // 64 MB  (tf32-rounded x)
__device__ float g_wqkvr[(size_t)Dn * QKV_N];     // 12 MB  (tf32-rounded Wqkv)
__device__ float g_woutr[(size_t)Dn * Dn];        // 4 MB   (tf32-rounded Wout)

__device__ __forceinline__ float round_tf32(float x) {
    unsigned u;
    asm("cvt.rn.tf32.f32 %0, %1;" : "=r"(u) : "f"(x));
    return __uint_as_float(u);
}

__device__ __forceinline__ void cp_async16(float* smem_dst, const float* gmem_src) {
    unsigned s = (unsigned)__cvta_generic_to_shared(smem_dst);
    asm volatile("cp.async.cg.shared.global [%0], [%1], 16;\n" :: "r"(s), "l"(gmem_src));
}
__device__ __forceinline__ void cp_commit() {
    asm volatile("cp.async.commit_group;\n" ::);
}
template<int N>
__device__ __forceinline__ void cp_wait() {
    asm volatile("cp.async.wait_group %0;\n" :: "n"(N));
}

// ---------------------------------------------------------------------------
// TF32 WMMA GEMM, 3-stage cp.async pipeline.
// Block tile 128x128, 4 warps (2x2), warp tile 64x64, 128 threads.
// 2 CTAs/SM co-residency: one CTA computes while the other syncs/loads.
// Inputs MUST be pre-rounded to tf32 (no in-loop cvt).
// ---------------------------------------------------------------------------
#define BM 128
#define BN 128
#define BK 32
#define STAGES 3
#define A_LD (BK + 4)            // 36 floats
#define B_LD (BN + 4)            // 132 floats
#define A_STAGE (BM * A_LD)      // 4608 floats
#define B_STAGE (BK * B_LD)      // 4224 floats
#define SMEM_FLOATS (STAGES * (A_STAGE + B_STAGE))
#define SMEM_BYTES (SMEM_FLOATS * 4)   // 105984 bytes (x2 CTAs = 207KB < 228KB)

__global__ __launch_bounds__(128, 2)
void gemm_tf32_pipe_kernel(const float* __restrict__ A,
                           const float* __restrict__ B,
                           float* __restrict__ C,
                           int M, int N, int K)
{
    extern __shared__ float smem[];
    float* As = smem;                         // [STAGES][BM][A_LD]
    float* Bs = smem + STAGES * A_STAGE;      // [STAGES][BK][B_LD]

    const int tid = threadIdx.x;
    const int warpId = tid >> 5;
    const int warpRow = warpId >> 1;      // 0..1  (64 rows each)
    const int warpCol = warpId & 1;       // 0..1  (64 cols each)

    const int rowBase = blockIdx.y * BM;
    const int colBase = blockIdx.x * BN;

    const int KT = K / BK;

    auto load_stage = [&](int kt, int stage) {
        const float* Ag = A + (size_t)rowBase * K + kt * BK;
        const float* Bg = B + (size_t)(kt * BK) * N + colBase;
        float* Asm = As + stage * A_STAGE;
        float* Bsm = Bs + stage * B_STAGE;
        // A tile: 128x32 floats = 1024 float4, 8 per thread
        #pragma unroll
        for (int i = 0; i < 8; i++) {
            int l = tid + i * 128;
            int ar = l >> 3, ac = (l & 7) << 2;
            cp_async16(Asm + ar * A_LD + ac, Ag + (size_t)ar * K + ac);
        }
        // B tile: 32x128 floats = 1024 float4, 8 per thread
        #pragma unroll
        for (int i = 0; i < 8; i++) {
            int l = tid + i * 128;
            int br = l >> 5, bc = (l & 31) << 2;
            cp_async16(Bsm + br * B_LD + bc, Bg + (size_t)br * N + bc);
        }
        cp_commit();
    };

    // Prefetch first STAGES-1 stages
    #pragma unroll
    for (int s = 0; s < STAGES - 1; s++)
        load_stage(s, s);

    wmma::fragment<wmma::accumulator, 16, 16, 8, float> acc[4][4];
    #pragma unroll
    for (int m = 0; m < 4; m++)
        #pragma unroll
        for (int n = 0; n < 4; n++)
            wmma::fill_fragment(acc[m][n], 0.0f);

    for (int kt = 0; kt < KT; kt++) {
        cp_wait<STAGES - 2>();
        __syncthreads();

        // Issue loads for the stage STAGES-1 ahead (overlaps with compute)
        if (kt + STAGES - 1 < KT)
            load_stage(kt + STAGES - 1, (kt + STAGES - 1) % STAGES);

        const float* Asm = As + (kt % STAGES) * A_STAGE;
        const float* Bsm = Bs + (kt % STAGES) * B_STAGE;

        #pragma unroll
        for (int kk = 0; kk < BK / 8; kk++) {
            wmma::fragment<wmma::matrix_a, 16, 16, 8, wmma::precision::tf32, wmma::row_major> af[4];
            wmma::fragment<wmma::matrix_b, 16, 16, 8, wmma::precision::tf32, wmma::row_major> bf[4];
            #pragma unroll
            for (int m = 0; m < 4; m++)
                wmma::load_matrix_sync(af[m], Asm + (warpRow * 64 + m * 16) * A_LD + kk * 8, A_LD);
            #pragma unroll
            for (int n = 0; n < 4; n++)
                wmma::load_matrix_sync(bf[n], Bsm + (kk * 8) * B_LD + warpCol * 64 + n * 16, B_LD);
            #pragma unroll
            for (int m = 0; m < 4; m++)
                #pragma unroll
                for (int n = 0; n < 4; n++)
                    wmma::mma_sync(acc[m][n], af[m], bf[n], acc[m][n]);
        }
        __syncthreads();
    }

    // Epilogue: direct global store
    #pragma unroll
    for (int m = 0; m < 4; m++) {
        #pragma unroll
        for (int n = 0; n < 4; n++) {
            int r = rowBase + warpRow * 64 + m * 16;
            int c = colBase + warpCol * 64 + n * 16;
            wmma::store_matrix_sync(C + (size_t)r * N + c, acc[m][n], N, wmma::mem_row_major);
        }
    }
}

// ---------------------------------------------------------------------------
// Elementwise tf32 RN rounding (pre-round GEMM operands)
// ---------------------------------------------------------------------------
__global__ void round_tf32_kernel(const float4* __restrict__ in,
                                  float4* __restrict__ out, int n4)
{
    int i = blockIdx.x * blockDim.x + threadIdx.x;
    if (i < n4) {
        float4 v = in[i];
        v.x = round_tf32(v.x); v.y = round_tf32(v.y);
        v.z = round_tf32(v.z); v.w = round_tf32(v.w);
        out[i] = v;
    }
}

// ---------------------------------------------------------------------------
// Per-token head-attention: one block per token. Output tf32-rounded
// (feeds GEMM2 without in-loop conversion).
// ---------------------------------------------------------------------------
__global__ __launch_bounds__(256, 8)
void attn_kernel(const float* __restrict__ qkv, float* __restrict__ out)
{
    __shared__ float sq[16 * 64];
    __shared__ float sk[16 * 65];
    __shared__ float sv[16 * 64];
    __shared__ float sattn[16 * 16];

    const int t = blockIdx.x;
    const float* base = qkv + (size_t)t * QKV_N;
    const int tid = threadIdx.x;

    #pragma unroll
    for (int idx = tid; idx < 1024; idx += 256) {
        int r = idx >> 6, d = idx & 63;
        sq[idx]        = base[idx];
        sk[r * 65 + d] = base[1024 + idx];
        sv[idx]        = base[2048 + idx];
    }
    __syncthreads();

    const int i = tid >> 4, j = tid & 15;
    float s = 0.0f;
    #pragma unroll
    for (int d = 0; d < 64; d++)
        s += sq[i * 64 + d] * sk[j * 65 + d];
    s *= 0.125f;

    float mx = s;
    #pragma unroll
    for (int off = 8; off; off >>= 1)
        mx = fmaxf(mx, __shfl_xor_sync(0xffffffffu, mx, off));
    float e = __expf(s - mx);
    float sum = e;
    #pragma unroll
    for (int off = 8; off; off >>= 1)
        sum += __shfl_xor_sync(0xffffffffu, sum, off);
    sattn[i * 16 + j] = e / sum;
    __syncthreads();

    #pragma unroll
    for (int idx = tid; idx < 1024; idx += 256) {
        int oi = idx >> 6, od = idx & 63;
        float acc = 0.0f;
        #pragma unroll
        for (int jj = 0; jj < 16; jj++)
            acc += sattn[oi * 16 + jj] * sv[jj * 64 + od];
        out[(size_t)t * Dn + idx] = round_tf32(acc);
    }
}

// ---------------------------------------------------------------------------
extern "C" void kernel_launch(void* const* d_in, const int* in_sizes, int n_in,
                              void* d_out, int out_size)
{
    const float* x    = (const float*)d_in[0];
    const float* Wqkv = (const float*)d_in[1];
    const float* Wout = (const float*)d_in[2];
    float* out = (float*)d_out;

    float *qkv_p, *attn_p, *xr_p, *wqkvr_p, *woutr_p;
    cudaGetSymbolAddress((void**)&qkv_p, g_qkv);
    cudaGetSymbolAddress((void**)&attn_p, g_attn);
    cudaGetSymbolAddress((void**)&xr_p, g_xr);
    cudaGetSymbolAddress((void**)&wqkvr_p, g_wqkvr);
    cudaGetSymbolAddress((void**)&woutr_p, g_woutr);

    static bool attr_set = false;
    if (!attr_set) {
        cudaFuncSetAttribute(gemm_tf32_pipe_kernel,
                             cudaFuncAttributeMaxDynamicSharedMemorySize, SMEM_BYTES);
        attr_set = true;
    }

    // Pre-round operands to tf32 (RN) once.
    {
        int n4x = (Mrows * Dn) / 4;
        round_tf32_kernel<<<(n4x + 255) / 256, 256>>>((const float4*)x, (float4*)xr_p, n4x);
        int n4q = (Dn * QKV_N) / 4;
        round_tf32_kernel<<<(n4q + 255) / 256, 256>>>((const float4*)Wqkv, (float4*)wqkvr_p, n4q);
        int n4o = (Dn * Dn) / 4;
        round_tf32_kernel<<<(n4o + 255) / 256, 256>>>((const float4*)Wout, (float4*)woutr_p, n4o);
    }

    // GEMM1: qkv = x @ Wqkv   (16384 x 3072, K=1024)
    {
        dim3 grid(QKV_N / BN, Mrows / BM);
        gemm_tf32_pipe_kernel<<<grid, 128, SMEM_BYTES>>>(xr_p, wqkvr_p, qkv_p,
                                                         Mrows, QKV_N, Dn);
    }

    // Attention per token
    attn_kernel<<<Mrows, 256>>>(qkv_p, attn_p);

    // GEMM2: out = attn @ Wout  (16384 x 1024, K=1024)
    {
        dim3 grid(Dn / BN, Mrows / BM);
        gemm_tf32_pipe_kernel<<<grid, 128, SMEM_BYTES>>>(attn_p, woutr_p, out,
                                                         Mrows, Dn, Dn);
    }
}